// round 1
// baseline (speedup 1.0000x reference)
#include <cuda_runtime.h>
#include <cuda_bf16.h>

#define NN 50000
#define NE 800000
#define NIDX 25000

// Scratch (no allocation allowed) — __device__ globals.
__device__ float g_deg [NN];
__device__ float g_aggr[NN * 16];
__device__ float g_h1  [NN * 16];
__device__ float g_h2  [NN * 16];

// ---------------------------------------------------------------------------
__global__ void zero_kernel(float* __restrict__ p, int n) {
    int i = blockIdx.x * blockDim.x + threadIdx.x;
    if (i < n) p[i] = 0.0f;
}

__global__ void degree_kernel(const int* __restrict__ ei, float* __restrict__ deg) {
    int e = blockIdx.x * blockDim.x + threadIdx.x;
    if (e < NE) atomicAdd(&deg[ei[NE + e]], 1.0f);
}

// ---------------------------------------------------------------------------
// Edge kernel: 16 lanes per edge (lane = output channel). 256 threads = 16 edges/block.
// Edge weight w[ci][co] = relu((pseudo . W[:,j] + b_j) * g_j + beta_j), j = ci*16+co,
// folded into float4 smem params: (W0*g, W1*g, W2*g, b*g+beta).
template<int CI>
__global__ void __launch_bounds__(256)
edge_kernel(const float* __restrict__ hin,   // [NN, CI]
            const float* __restrict__ pos,   // [NN, 3]
            const int*   __restrict__ ei,    // [2, NE]
            const float* __restrict__ lin_w, // [3, CI*16]
            const float* __restrict__ lin_b, // [CI*16]
            const float* __restrict__ gamma, // [CI*16]
            const float* __restrict__ beta,  // [CI*16]
            float* __restrict__ aggr)        // [NN, 16]
{
    constexpr int D = CI * 16;
    __shared__ float4 sP[D];

    int t = threadIdx.x;
    for (int j = t; j < D; j += 256) {
        float g = gamma[j];
        sP[j] = make_float4(lin_w[j] * g, lin_w[D + j] * g, lin_w[2 * D + j] * g,
                            fmaf(lin_b[j], g, beta[j]));
    }
    __syncthreads();

    int lane = t & 15;
    int e = (blockIdx.x * 256 + t) >> 4;
    if (e >= NE) return;

    int src = ei[e];
    int dst = ei[NE + e];

    float p0 = pos[dst * 3 + 0] - pos[src * 3 + 0];
    float p1 = pos[dst * 3 + 1] - pos[src * 3 + 1];
    float p2 = pos[dst * 3 + 2] - pos[src * 3 + 2];

    float myx = (lane < CI) ? hin[src * CI + lane] : 0.0f;

    float acc = 0.0f;
#pragma unroll
    for (int ci = 0; ci < CI; ci++) {
        float xv = __shfl_sync(0xffffffffu, myx, ci, 16);
        float4 P = sP[ci * 16 + lane];
        float w = fmaf(p0, P.x, fmaf(p1, P.y, fmaf(p2, P.z, P.w)));
        w = fmaxf(w, 0.0f);
        acc = fmaf(xv, w, acc);
    }

    atomicAdd(&aggr[dst * 16 + lane], acc);
}

// ---------------------------------------------------------------------------
// Node kernel: h_out[n,c] = relu(aggr[n,c]/max(deg,1) + sum_ci h_in[n,ci]*root[ci,c] + bias[c])
template<int CI>
__global__ void __launch_bounds__(256)
node_kernel(const float* __restrict__ hin,
            const float* __restrict__ aggr,
            const float* __restrict__ deg,
            const float* __restrict__ root,  // [CI, 16]
            const float* __restrict__ bias,  // [16]
            float* __restrict__ hout)        // [NN, 16]
{
    int i = blockIdx.x * blockDim.x + threadIdx.x;
    if (i >= NN * 16) return;
    int n = i >> 4, c = i & 15;
    float inv = 1.0f / fmaxf(deg[n], 1.0f);
    float v = fmaf(aggr[i], inv, bias[c]);
#pragma unroll
    for (int ci = 0; ci < CI; ci++)
        v = fmaf(hin[n * CI + ci], root[ci * 16 + c], v);
    hout[i] = fmaxf(v, 0.0f);
}

// ---------------------------------------------------------------------------
// Output: [h[idx] (25000x16), pos[idx] (25000x3), batch[idx] (25000)] flattened.
__global__ void gather_kernel(const float* __restrict__ h,
                              const float* __restrict__ pos,
                              const int*   __restrict__ batch,
                              const int*   __restrict__ idx,
                              float* __restrict__ out)
{
    int i = blockIdx.x * blockDim.x + threadIdx.x;
    if (i >= NIDX) return;
    int n = idx[i];
#pragma unroll
    for (int c = 0; c < 16; c++) out[i * 16 + c] = h[n * 16 + c];
    out[NIDX * 16 + i * 3 + 0] = pos[n * 3 + 0];
    out[NIDX * 16 + i * 3 + 1] = pos[n * 3 + 1];
    out[NIDX * 16 + i * 3 + 2] = pos[n * 3 + 2];
    // batch is int32 (all zeros in this dataset); bit-copy preserves either view.
    reinterpret_cast<int*>(out)[NIDX * 19 + i] = batch[n];
}

// ---------------------------------------------------------------------------
extern "C" void kernel_launch(void* const* d_in, const int* in_sizes, int n_in,
                              void* d_out, int out_size)
{
    const float* x      = (const float*)d_in[0];
    const float* pos    = (const float*)d_in[1];
    // per-layer params: lin_w, lin_b, gamma, beta, root, bias at d_in[2+6i .. 7+6i]
    const float* lw0 = (const float*)d_in[2],  *lb0 = (const float*)d_in[3],
               * g0  = (const float*)d_in[4],  *be0 = (const float*)d_in[5],
               * r0  = (const float*)d_in[6],  *bi0 = (const float*)d_in[7];
    const float* lw1 = (const float*)d_in[8],  *lb1 = (const float*)d_in[9],
               * g1  = (const float*)d_in[10], *be1 = (const float*)d_in[11],
               * r1  = (const float*)d_in[12], *bi1 = (const float*)d_in[13];
    const float* lw2 = (const float*)d_in[14], *lb2 = (const float*)d_in[15],
               * g2  = (const float*)d_in[16], *be2 = (const float*)d_in[17],
               * r2  = (const float*)d_in[18], *bi2 = (const float*)d_in[19];
    const int* batch = (const int*)d_in[20];
    const int* idx   = (const int*)d_in[21];
    const int* ei    = (const int*)d_in[22];
    float* out = (float*)d_out;

    float *deg, *aggr, *h1, *h2;
    cudaGetSymbolAddress((void**)&deg,  g_deg);
    cudaGetSymbolAddress((void**)&aggr, g_aggr);
    cudaGetSymbolAddress((void**)&h1,   g_h1);
    cudaGetSymbolAddress((void**)&h2,   g_h2);

    const int ZB = 256;
    dim3 edge_grid(NE / 16);          // 50000 blocks, 16 edges/block
    dim3 node_grid((NN * 16 + 255) / 256);
    dim3 ek_grid((NE + 255) / 256);

    // Degree (once)
    zero_kernel<<<(NN + ZB - 1) / ZB, ZB>>>(deg, NN);
    degree_kernel<<<ek_grid, 256>>>(ei, deg);

    // Layer 0 (CI=8): x -> h1
    zero_kernel<<<(NN * 16 + ZB - 1) / ZB, ZB>>>(aggr, NN * 16);
    edge_kernel<8><<<edge_grid, 256>>>(x, pos, ei, lw0, lb0, g0, be0, aggr);
    node_kernel<8><<<node_grid, 256>>>(x, aggr, deg, r0, bi0, h1);

    // Layer 1 (CI=16): h1 -> h2
    zero_kernel<<<(NN * 16 + ZB - 1) / ZB, ZB>>>(aggr, NN * 16);
    edge_kernel<16><<<edge_grid, 256>>>(h1, pos, ei, lw1, lb1, g1, be1, aggr);
    node_kernel<16><<<node_grid, 256>>>(h1, aggr, deg, r1, bi1, h2);

    // Layer 2 (CI=16): h2 -> h1
    zero_kernel<<<(NN * 16 + ZB - 1) / ZB, ZB>>>(aggr, NN * 16);
    edge_kernel<16><<<edge_grid, 256>>>(h2, pos, ei, lw2, lb2, g2, be2, aggr);
    node_kernel<16><<<node_grid, 256>>>(h2, aggr, deg, r2, bi2, h1);

    // Gather output
    gather_kernel<<<(NIDX + 255) / 256, 256>>>(h1, pos, batch, idx, out);
}

// round 2
// speedup vs baseline: 1.4604x; 1.4604x over previous
#include <cuda_runtime.h>
#include <cuda_bf16.h>

#define NN 50000
#define NE 800000
#define NIDX 25000

typedef unsigned long long ull;

// Scratch (__device__ globals; zero-initialized at module load).
__device__ float  g_deg [NN];
__device__ float  g_aggr[NN * 16];      // invariant: zero at start & end of every call
__device__ float  g_h1  [NN * 16];
__device__ float  g_h2  [NN * 16];
__device__ float4 g_pseudo[NE];
__device__ int2   g_sd   [NE];
__device__ ull    g_fold [3][512];      // packed folded edge-MLP params per layer

// ---- packed f32x2 helpers -------------------------------------------------
__device__ __forceinline__ ull ffma2(ull a, ull b, ull c) {
    ull d;
    asm("fma.rn.f32x2 %0, %1, %2, %3;" : "=l"(d) : "l"(a), "l"(b), "l"(c));
    return d;
}
__device__ __forceinline__ ull pack2(float lo, float hi) {
    ull r;
    asm("mov.b64 %0, {%1, %2};" : "=l"(r) : "f"(lo), "f"(hi));
    return r;
}
__device__ __forceinline__ void unpack2(ull v, float& lo, float& hi) {
    asm("mov.b64 {%0, %1}, %2;" : "=f"(lo), "=f"(hi) : "l"(v));
}
__device__ __forceinline__ ull relu2(ull v) {
    float lo, hi;
    unpack2(v, lo, hi);
    lo = fmaxf(lo, 0.0f);
    hi = fmaxf(hi, 0.0f);
    return pack2(lo, hi);
}

// ---------------------------------------------------------------------------
__global__ void zero_deg_kernel() {
    int i = blockIdx.x * blockDim.x + threadIdx.x;
    if (i < NN) g_deg[i] = 0.0f;
}

// Prep: pseudo = pos[dst]-pos[src], packed (src,dst), degree via atomics.
__global__ void prep_kernel(const float* __restrict__ pos, const int* __restrict__ ei) {
    int e = blockIdx.x * blockDim.x + threadIdx.x;
    if (e >= NE) return;
    int s = ei[e];
    int d = ei[NE + e];
    float4 ps;
    ps.x = pos[d * 3 + 0] - pos[s * 3 + 0];
    ps.y = pos[d * 3 + 1] - pos[s * 3 + 1];
    ps.z = pos[d * 3 + 2] - pos[s * 3 + 2];
    ps.w = 0.0f;
    g_pseudo[e] = ps;
    g_sd[e] = make_int2(s, d);
    atomicAdd(&g_deg[d], 1.0f);
}

// Fold edge-MLP params: P = (Wx*g, Wy*g, Wz*g, b*g+beta), packed over ci-pairs.
// Layout (as floats): fold[((k*4+c)*16+co)*2 + (ci&1)], k = ci>>1.
__global__ void fold_kernel(const float* __restrict__ lw0, const float* __restrict__ lb0,
                            const float* __restrict__ ga0, const float* __restrict__ be0,
                            const float* __restrict__ lw1, const float* __restrict__ lb1,
                            const float* __restrict__ ga1, const float* __restrict__ be1,
                            const float* __restrict__ lw2, const float* __restrict__ lb2,
                            const float* __restrict__ ga2, const float* __restrict__ be2)
{
    int L = blockIdx.x;
    const float *lw = (L == 0) ? lw0 : (L == 1) ? lw1 : lw2;
    const float *lb = (L == 0) ? lb0 : (L == 1) ? lb1 : lb2;
    const float *ga = (L == 0) ? ga0 : (L == 1) ? ga1 : ga2;
    const float *be = (L == 0) ? be0 : (L == 1) ? be1 : be2;
    int D = (L == 0) ? 128 : 256;
    float* fb = (float*)g_fold[L];
    for (int j = threadIdx.x; j < D; j += blockDim.x) {
        float g = ga[j];
        float c0 = lw[j] * g;
        float c1 = lw[D + j] * g;
        float c2 = lw[2 * D + j] * g;
        float c3 = fmaf(lb[j], g, be[j]);
        int ci = j >> 4, co = j & 15;
        int k = ci >> 1, h = ci & 1;
        fb[((k * 4 + 0) * 16 + co) * 2 + h] = c0;
        fb[((k * 4 + 1) * 16 + co) * 2 + h] = c1;
        fb[((k * 4 + 2) * 16 + co) * 2 + h] = c2;
        fb[((k * 4 + 3) * 16 + co) * 2 + h] = c3;
    }
}

// ---------------------------------------------------------------------------
// Edge kernel: 16 lanes per edge (lane = co), grid-stride over edges.
// Params live in registers, packed over ci-pairs; inner math is fma.rn.f32x2.
template<int CI>
__global__ void __launch_bounds__(256)
edge_kernel(const float* __restrict__ hin,   // [NN, CI]
            const ull*   __restrict__ fold,  // packed params [KK][4][16]
            float*       __restrict__ aggr)  // [NN, 16]
{
    constexpr int KK = CI / 2;
    int t  = blockIdx.x * blockDim.x + threadIdx.x;
    int co = threadIdx.x & 15;

    // Load packed params into registers (coalesced: adjacent co -> adjacent u64).
    ull Px[KK], Py[KK], Pz[KK], Pc[KK];
#pragma unroll
    for (int k = 0; k < KK; k++) {
        Px[k] = __ldg(&fold[((k * 4 + 0) * 16) + co]);
        Py[k] = __ldg(&fold[((k * 4 + 1) * 16) + co]);
        Pz[k] = __ldg(&fold[((k * 4 + 2) * 16) + co]);
        Pc[k] = __ldg(&fold[((k * 4 + 3) * 16) + co]);
    }

    int slot   = t >> 4;
    int nslots = (gridDim.x * blockDim.x) >> 4;

    for (int e = slot; e < NE; e += nslots) {
        int2   sd = __ldg(&g_sd[e]);
        float4 ps = __ldg(&g_pseudo[e]);
        ull p0 = pack2(ps.x, ps.x);
        ull p1 = pack2(ps.y, ps.y);
        ull p2 = pack2(ps.z, ps.z);

        // x[src] row as packed ci-pairs (broadcast across the half-warp).
        ull xv[KK];
        const ulonglong2* xr = (const ulonglong2*)(hin + (size_t)sd.x * CI);
#pragma unroll
        for (int q = 0; q < KK / 2; q++) {
            ulonglong2 v = __ldg(&xr[q]);
            xv[2 * q]     = v.x;
            xv[2 * q + 1] = v.y;
        }

        ull acc = pack2(0.0f, 0.0f);
#pragma unroll
        for (int k = 0; k < KK; k++) {
            ull w = ffma2(p2, Pz[k], Pc[k]);
            w = ffma2(p1, Py[k], w);
            w = ffma2(p0, Px[k], w);
            w = relu2(w);
            acc = ffma2(xv[k], w, acc);
        }
        float lo, hi;
        unpack2(acc, lo, hi);
        atomicAdd(&aggr[(size_t)sd.y * 16 + co], lo + hi);
    }
}

// ---------------------------------------------------------------------------
// Node kernel: one thread per node, 16 channels in registers.
// h_out = relu(aggr/max(deg,1) + h_in @ root + bias); also re-zeroes aggr.
template<int CI>
__global__ void __launch_bounds__(256)
node_kernel(const float* __restrict__ hin,
            const float* __restrict__ root,  // [CI, 16]
            const float* __restrict__ bias,  // [16]
            float* __restrict__ aggr,
            float* __restrict__ hout)        // [NN, 16]
{
    int n = blockIdx.x * blockDim.x + threadIdx.x;
    if (n >= NN) return;
    float inv = 1.0f / fmaxf(g_deg[n], 1.0f);

    float acc[16];
    float4* ar = (float4*)(aggr + (size_t)n * 16);
#pragma unroll
    for (int q = 0; q < 4; q++) {
        float4 a = ar[q];
        acc[4 * q + 0] = fmaf(a.x, inv, bias[4 * q + 0]);
        acc[4 * q + 1] = fmaf(a.y, inv, bias[4 * q + 1]);
        acc[4 * q + 2] = fmaf(a.z, inv, bias[4 * q + 2]);
        acc[4 * q + 3] = fmaf(a.w, inv, bias[4 * q + 3]);
    }
#pragma unroll
    for (int ci = 0; ci < CI; ci++) {
        float xv = hin[(size_t)n * CI + ci];
#pragma unroll
        for (int c = 0; c < 16; c++)
            acc[c] = fmaf(xv, __ldg(&root[ci * 16 + c]), acc[c]);
    }
    float4* orow = (float4*)(hout + (size_t)n * 16);
    float4 z = make_float4(0.f, 0.f, 0.f, 0.f);
#pragma unroll
    for (int q = 0; q < 4; q++) {
        float4 o;
        o.x = fmaxf(acc[4 * q + 0], 0.0f);
        o.y = fmaxf(acc[4 * q + 1], 0.0f);
        o.z = fmaxf(acc[4 * q + 2], 0.0f);
        o.w = fmaxf(acc[4 * q + 3], 0.0f);
        orow[q] = o;
        ar[q] = z;   // reset aggr for the next layer / next call
    }
}

// ---------------------------------------------------------------------------
__global__ void gather_kernel(const float* __restrict__ h,
                              const float* __restrict__ pos,
                              const int*   __restrict__ batch,
                              const int*   __restrict__ idx,
                              float* __restrict__ out)
{
    int i = blockIdx.x * blockDim.x + threadIdx.x;
    if (i >= NIDX) return;
    int n = idx[i];
    float4* od = (float4*)(out + (size_t)i * 16);
    const float4* hs = (const float4*)(h + (size_t)n * 16);
#pragma unroll
    for (int q = 0; q < 4; q++) od[q] = hs[q];
    out[NIDX * 16 + i * 3 + 0] = pos[n * 3 + 0];
    out[NIDX * 16 + i * 3 + 1] = pos[n * 3 + 1];
    out[NIDX * 16 + i * 3 + 2] = pos[n * 3 + 2];
    reinterpret_cast<int*>(out)[NIDX * 19 + i] = batch[n];
}

// ---------------------------------------------------------------------------
extern "C" void kernel_launch(void* const* d_in, const int* in_sizes, int n_in,
                              void* d_out, int out_size)
{
    const float* x   = (const float*)d_in[0];
    const float* pos = (const float*)d_in[1];
    const float* lw0 = (const float*)d_in[2],  *lb0 = (const float*)d_in[3],
               * g0  = (const float*)d_in[4],  *be0 = (const float*)d_in[5],
               * r0  = (const float*)d_in[6],  *bi0 = (const float*)d_in[7];
    const float* lw1 = (const float*)d_in[8],  *lb1 = (const float*)d_in[9],
               * g1  = (const float*)d_in[10], *be1 = (const float*)d_in[11],
               * r1  = (const float*)d_in[12], *bi1 = (const float*)d_in[13];
    const float* lw2 = (const float*)d_in[14], *lb2 = (const float*)d_in[15],
               * g2  = (const float*)d_in[16], *be2 = (const float*)d_in[17],
               * r2  = (const float*)d_in[18], *bi2 = (const float*)d_in[19];
    const int* batch = (const int*)d_in[20];
    const int* idx   = (const int*)d_in[21];
    const int* ei    = (const int*)d_in[22];
    float* out = (float*)d_out;

    float *aggr, *h1, *h2;
    ull* fold;
    cudaGetSymbolAddress((void**)&aggr, g_aggr);
    cudaGetSymbolAddress((void**)&h1,   g_h1);
    cudaGetSymbolAddress((void**)&h2,   g_h2);
    cudaGetSymbolAddress((void**)&fold, g_fold);

    dim3 node_grid((NN + 255) / 256);
    dim3 prep_grid((NE + 255) / 256);
    const int EDGE_BLOCKS = 1024;

    fold_kernel<<<3, 256>>>(lw0, lb0, g0, be0, lw1, lb1, g1, be1, lw2, lb2, g2, be2);
    zero_deg_kernel<<<node_grid, 256>>>();
    prep_kernel<<<prep_grid, 256>>>(pos, ei);

    // Layer 0 (CI=8): x -> h1   (aggr starts zero; node kernel re-zeroes it)
    edge_kernel<8><<<EDGE_BLOCKS, 256>>>(x, fold + 0 * 512, aggr);
    node_kernel<8><<<node_grid, 256>>>(x, r0, bi0, aggr, h1);

    // Layer 1 (CI=16): h1 -> h2
    edge_kernel<16><<<EDGE_BLOCKS, 256>>>(h1, fold + 1 * 512, aggr);
    node_kernel<16><<<node_grid, 256>>>(h1, r1, bi1, aggr, h2);

    // Layer 2 (CI=16): h2 -> h1
    edge_kernel<16><<<EDGE_BLOCKS, 256>>>(h2, fold + 2 * 512, aggr);
    node_kernel<16><<<node_grid, 256>>>(h2, r2, bi2, aggr, h1);

    gather_kernel<<<(NIDX + 255) / 256, 256>>>(h1, pos, batch, idx, out);
}